// round 3
// baseline (speedup 1.0000x reference)
#include <cuda_runtime.h>
#include <math.h>

#define N_NODES 50000
#define N_EDGES 800000
#define ET (N_EDGES + N_NODES)

// ---------------- scratch (static device globals; no allocation) ----------------
__device__ float g_h1[(size_t)N_NODES * 128];    // x @ W1
__device__ float g_out1[(size_t)N_NODES * 128];  // layer1 output (post bias+relu)
__device__ float g_h2[(size_t)N_NODES * 64];     // out1 @ W2
__device__ float g_ss1[N_NODES * 4];
__device__ float g_sd1[N_NODES * 4];
__device__ float g_ss2[N_NODES];
__device__ float g_sd2[N_NODES];
__device__ int   g_deg[N_NODES];
__device__ int   g_off[N_NODES + 1];
__device__ int   g_pos[N_NODES];
__device__ int   g_esrc[ET];
__device__ int   g_chunk[64];

__device__ __forceinline__ float lrelu(float x) {
    return x > 0.f ? x : 0.2f * x;
}

// edge_index arrives as int32 on device (harness dtype contract: int64 -> int32).
// Layout [2, E] row-major: row 0 = src, row 1 = dst. Clamp defensively so a
// dtype surprise yields finite wrong values instead of a device trap.
__device__ __forceinline__ void get_edge(const int* __restrict__ ei, int i,
                                         int& s, int& d) {
    if (i < N_EDGES) {
        s = ei[i];
        d = ei[N_EDGES + i];
        s = min(max(s, 0), N_NODES - 1);
        d = min(max(d, 0), N_NODES - 1);
    } else {
        s = d = i - N_EDGES;
    }
}

// ---------------- CSR build ----------------
__global__ void zero_deg_kernel() {
    int i = blockIdx.x * blockDim.x + threadIdx.x;
    if (i < N_NODES) g_deg[i] = 0;
}

__global__ void hist_kernel(const int* __restrict__ ei) {
    int i = blockIdx.x * blockDim.x + threadIdx.x;
    if (i < ET) {
        int s, d;
        get_edge(ei, i, s, d);
        atomicAdd(&g_deg[d], 1);
    }
}

__global__ void scan1_kernel() {
    __shared__ int sm[1024];
    int i = blockIdx.x * 1024 + threadIdx.x;
    int v = (i < N_NODES) ? g_deg[i] : 0;
    sm[threadIdx.x] = v;
    __syncthreads();
#pragma unroll
    for (int o = 1; o < 1024; o <<= 1) {
        int t = (threadIdx.x >= o) ? sm[threadIdx.x - o] : 0;
        __syncthreads();
        sm[threadIdx.x] += t;
        __syncthreads();
    }
    if (i < N_NODES) g_off[i] = sm[threadIdx.x] - v;  // exclusive within chunk
    if (threadIdx.x == 1023) g_chunk[blockIdx.x] = sm[1023];
}

__global__ void scan2_kernel(int nch) {
    if (threadIdx.x == 0 && blockIdx.x == 0) {
        int acc = 0;
        for (int i = 0; i < nch; i++) {
            int t = g_chunk[i];
            g_chunk[i] = acc;
            acc += t;
        }
    }
}

__global__ void scan3_kernel() {
    int i = blockIdx.x * blockDim.x + threadIdx.x;
    if (i < N_NODES) {
        g_off[i] += g_chunk[i >> 10];
        g_pos[i] = 0;
    }
    if (i == 0) g_off[N_NODES] = ET;
}

__global__ void scatter_kernel(const int* __restrict__ ei) {
    int i = blockIdx.x * blockDim.x + threadIdx.x;
    if (i < ET) {
        int s, d;
        get_edge(ei, i, s, d);
        int p = atomicAdd(&g_pos[d], 1);
        g_esrc[g_off[d] + p] = s;
    }
}

// ---------------- SGEMM body (row-major, C = A[MxK] @ B[KxN]) ----------------
template <int BM, int BN, int BK, int TM, int TN>
__device__ __forceinline__ void sgemm_body(const float* __restrict__ A,
                                           const float* __restrict__ B,
                                           float* __restrict__ C,
                                           int M, int N, int K) {
    constexpr int THREADS = (BM / TM) * (BN / TN);
    __shared__ float As[BK][BM];
    __shared__ float Bs[BK][BN];
    const int tid = threadIdx.x;
    const int row0 = blockIdx.x * BM;
    const int col0 = blockIdx.y * BN;
    const int tr = tid / (BN / TN);
    const int tc = tid % (BN / TN);

    float acc[TM][TN] = {};

    constexpr int A_LOADS = (BM * BK) / (THREADS * 4);
    constexpr int B_LOADS = (BK * BN) / (THREADS * 4);

    for (int kt = 0; kt < K; kt += BK) {
#pragma unroll
        for (int i = 0; i < A_LOADS; i++) {
            int idx = (tid + i * THREADS) * 4;
            int am = idx / BK, ak = idx % BK;
            float4 v = make_float4(0.f, 0.f, 0.f, 0.f);
            if (row0 + am < M)
                v = *(const float4*)(A + (size_t)(row0 + am) * K + kt + ak);
            As[ak + 0][am] = v.x;
            As[ak + 1][am] = v.y;
            As[ak + 2][am] = v.z;
            As[ak + 3][am] = v.w;
        }
#pragma unroll
        for (int i = 0; i < B_LOADS; i++) {
            int idx = (tid + i * THREADS) * 4;
            int bk = idx / BN, bn = idx % BN;
            *(float4*)&Bs[bk][bn] = *(const float4*)(B + (size_t)(kt + bk) * N + col0 + bn);
        }
        __syncthreads();
#pragma unroll
        for (int k = 0; k < BK; k++) {
            float ra[TM], rb[TN];
#pragma unroll
            for (int i = 0; i < TM; i++) ra[i] = As[k][tr * TM + i];
#pragma unroll
            for (int j = 0; j < TN; j++) rb[j] = Bs[k][tc * TN + j];
#pragma unroll
            for (int i = 0; i < TM; i++)
#pragma unroll
                for (int j = 0; j < TN; j++) acc[i][j] = fmaf(ra[i], rb[j], acc[i][j]);
        }
        __syncthreads();
    }
#pragma unroll
    for (int i = 0; i < TM; i++) {
        int row = row0 + tr * TM + i;
        if (row < M) {
#pragma unroll
            for (int j = 0; j < TN; j += 4) {
                float4 v = make_float4(acc[i][j], acc[i][j + 1], acc[i][j + 2],
                                       acc[i][j + 3]);
                *(float4*)(C + (size_t)row * N + col0 + tc * TN + j) = v;
            }
        }
    }
}

// GEMM wrappers binding __device__ globals inside device code (no host symbol lookup)
__global__ void gemm1_kernel(const float* __restrict__ x, const float* __restrict__ W1) {
    sgemm_body<64, 128, 16, 4, 8>(x, W1, g_h1, N_NODES, 128, 128);
}

__global__ void gemm2_kernel(const float* __restrict__ W2) {
    sgemm_body<64, 64, 16, 4, 4>(g_out1, W2, g_h2, N_NODES, 64, 128);
}

// ---------------- attention scores ----------------
// Layer1: 4 heads x 32 ch. One warp per node; lane l covers channels [4l, 4l+4).
__global__ void scores1_kernel(const float* __restrict__ a_src,
                               const float* __restrict__ a_dst) {
    int gid = blockIdx.x * blockDim.x + threadIdx.x;
    int node = gid >> 5;
    int lane = threadIdx.x & 31;
    if (node >= N_NODES) return;
    float4 v = *(const float4*)&g_h1[(size_t)node * 128 + lane * 4];
    int head = lane >> 3;
    int cb = (lane & 7) * 4;
    const float* as = a_src + head * 32 + cb;
    const float* ad = a_dst + head * 32 + cb;
    float ps = v.x * as[0] + v.y * as[1] + v.z * as[2] + v.w * as[3];
    float pd = v.x * ad[0] + v.y * ad[1] + v.z * ad[2] + v.w * ad[3];
#pragma unroll
    for (int o = 4; o; o >>= 1) {
        ps += __shfl_xor_sync(0xffffffffu, ps, o);
        pd += __shfl_xor_sync(0xffffffffu, pd, o);
    }
    if ((lane & 7) == 0) {
        g_ss1[node * 4 + head] = ps;
        g_sd1[node * 4 + head] = pd;
    }
}

// Layer2: 1 head x 64 ch. One warp per node; lane l covers channels [2l, 2l+2).
__global__ void scores2_kernel(const float* __restrict__ a_src,
                               const float* __restrict__ a_dst) {
    int gid = blockIdx.x * blockDim.x + threadIdx.x;
    int node = gid >> 5;
    int lane = threadIdx.x & 31;
    if (node >= N_NODES) return;
    float2 v = *(const float2*)&g_h2[(size_t)node * 64 + lane * 2];
    float ps = v.x * a_src[lane * 2] + v.y * a_src[lane * 2 + 1];
    float pd = v.x * a_dst[lane * 2] + v.y * a_dst[lane * 2 + 1];
#pragma unroll
    for (int o = 16; o; o >>= 1) {
        ps += __shfl_xor_sync(0xffffffffu, ps, o);
        pd += __shfl_xor_sync(0xffffffffu, pd, o);
    }
    if (lane == 0) {
        g_ss2[node] = ps;
        g_sd2[node] = pd;
    }
}

// ---------------- aggregation layer 1 (4 heads x 32ch, out 128, bias+relu) -------
__global__ void agg1_kernel(const float* __restrict__ bias) {
    const int n = blockIdx.x;
    const int tid = threadIdx.x;
    const int beg = g_off[n];
    const int deg = g_off[n + 1] - beg;

    __shared__ int   sh_src[32];
    __shared__ float sh_alpha[32][4];

    float sd0 = 0.f, sd1 = 0.f, sd2 = 0.f, sd3 = 0.f;
    float m0 = -1e30f, m1 = -1e30f, m2 = -1e30f, m3 = -1e30f;
    float d0 = 0.f, d1 = 0.f, d2 = 0.f, d3 = 0.f;

    if (tid < 32) {
        float4 sv = *(const float4*)(g_sd1 + n * 4);
        sd0 = sv.x; sd1 = sv.y; sd2 = sv.z; sd3 = sv.w;
        for (int j = tid; j < deg; j += 32) {
            int s = g_esrc[beg + j];
            float4 ss = *(const float4*)(g_ss1 + s * 4);
            float e0 = lrelu(ss.x + sd0);
            float e1 = lrelu(ss.y + sd1);
            float e2 = lrelu(ss.z + sd2);
            float e3 = lrelu(ss.w + sd3);
            if (e0 > m0) { d0 = d0 * __expf(m0 - e0) + 1.f; m0 = e0; } else d0 += __expf(e0 - m0);
            if (e1 > m1) { d1 = d1 * __expf(m1 - e1) + 1.f; m1 = e1; } else d1 += __expf(e1 - m1);
            if (e2 > m2) { d2 = d2 * __expf(m2 - e2) + 1.f; m2 = e2; } else d2 += __expf(e2 - m2);
            if (e3 > m3) { d3 = d3 * __expf(m3 - e3) + 1.f; m3 = e3; } else d3 += __expf(e3 - m3);
        }
#pragma unroll
        for (int o = 16; o; o >>= 1) {
            float mo, dd, mn;
            mo = __shfl_xor_sync(0xffffffffu, m0, o); dd = __shfl_xor_sync(0xffffffffu, d0, o);
            mn = fmaxf(m0, mo); d0 = d0 * __expf(m0 - mn) + dd * __expf(mo - mn); m0 = mn;
            mo = __shfl_xor_sync(0xffffffffu, m1, o); dd = __shfl_xor_sync(0xffffffffu, d1, o);
            mn = fmaxf(m1, mo); d1 = d1 * __expf(m1 - mn) + dd * __expf(mo - mn); m1 = mn;
            mo = __shfl_xor_sync(0xffffffffu, m2, o); dd = __shfl_xor_sync(0xffffffffu, d2, o);
            mn = fmaxf(m2, mo); d2 = d2 * __expf(m2 - mn) + dd * __expf(mo - mn); m2 = mn;
            mo = __shfl_xor_sync(0xffffffffu, m3, o); dd = __shfl_xor_sync(0xffffffffu, d3, o);
            mn = fmaxf(m3, mo); d3 = d3 * __expf(m3 - mn) + dd * __expf(mo - mn); m3 = mn;
        }
        d0 = 1.f / d0; d1 = 1.f / d1; d2 = 1.f / d2; d3 = 1.f / d3;  // now inverse denom
    }

    const int head = tid >> 5;
    float acc = 0.f;
    for (int j0 = 0; j0 < deg; j0 += 32) {
        int cnt = min(32, deg - j0);
        __syncthreads();
        if (tid < cnt) {
            int s = g_esrc[beg + j0 + tid];
            sh_src[tid] = s;
            float4 ss = *(const float4*)(g_ss1 + s * 4);
            sh_alpha[tid][0] = __expf(lrelu(ss.x + sd0) - m0) * d0;
            sh_alpha[tid][1] = __expf(lrelu(ss.y + sd1) - m1) * d1;
            sh_alpha[tid][2] = __expf(lrelu(ss.z + sd2) - m2) * d2;
            sh_alpha[tid][3] = __expf(lrelu(ss.w + sd3) - m3) * d3;
        }
        __syncthreads();
#pragma unroll 4
        for (int j = 0; j < cnt; j++) {
            acc = fmaf(sh_alpha[j][head], g_h1[(size_t)sh_src[j] * 128 + tid], acc);
        }
    }
    float r = acc + bias[tid];
    g_out1[(size_t)n * 128 + tid] = fmaxf(r, 0.f);  // fused relu
}

// ---------------- aggregation layer 2 (1 head x 64ch, writes d_out + bias) -------
__global__ void agg2_kernel(const float* __restrict__ bias, float* __restrict__ out) {
    const int n = blockIdx.x;
    const int tid = threadIdx.x;
    const int beg = g_off[n];
    const int deg = g_off[n + 1] - beg;

    __shared__ int   sh_src[32];
    __shared__ float sh_alpha[32];

    float sd = 0.f;
    float m = -1e30f, d = 0.f;

    if (tid < 32) {
        sd = g_sd2[n];
        for (int j = tid; j < deg; j += 32) {
            int s = g_esrc[beg + j];
            float e = lrelu(g_ss2[s] + sd);
            if (e > m) { d = d * __expf(m - e) + 1.f; m = e; } else d += __expf(e - m);
        }
#pragma unroll
        for (int o = 16; o; o >>= 1) {
            float mo = __shfl_xor_sync(0xffffffffu, m, o);
            float dd = __shfl_xor_sync(0xffffffffu, d, o);
            float mn = fmaxf(m, mo);
            d = d * __expf(m - mn) + dd * __expf(mo - mn);
            m = mn;
        }
        d = 1.f / d;
    }

    float acc = 0.f;
    for (int j0 = 0; j0 < deg; j0 += 32) {
        int cnt = min(32, deg - j0);
        __syncthreads();
        if (tid < cnt) {
            int s = g_esrc[beg + j0 + tid];
            sh_src[tid] = s;
            sh_alpha[tid] = __expf(lrelu(g_ss2[s] + sd) - m) * d;
        }
        __syncthreads();
#pragma unroll 4
        for (int j = 0; j < cnt; j++) {
            acc = fmaf(sh_alpha[j], g_h2[(size_t)sh_src[j] * 64 + tid], acc);
        }
    }
    out[(size_t)n * 64 + tid] = acc + bias[tid];
}

// ---------------- launch ----------------
extern "C" void kernel_launch(void* const* d_in, const int* in_sizes, int n_in,
                              void* d_out, int out_size) {
    const float* x   = (const float*)d_in[0];
    const int*   ei  = (const int*)d_in[1];   // int64 in reference -> int32 on device
    const float* W1  = (const float*)d_in[2];
    const float* as1 = (const float*)d_in[3];
    const float* ad1 = (const float*)d_in[4];
    const float* b1  = (const float*)d_in[5];
    const float* W2  = (const float*)d_in[6];
    const float* as2 = (const float*)d_in[7];
    const float* ad2 = (const float*)d_in[8];
    const float* b2  = (const float*)d_in[9];
    float* out = (float*)d_out;

    const int NCH = (N_NODES + 1023) / 1024;  // 49

    // CSR build (graph is identical for both layers)
    zero_deg_kernel<<<(N_NODES + 255) / 256, 256>>>();
    hist_kernel<<<(ET + 255) / 256, 256>>>(ei);
    scan1_kernel<<<NCH, 1024>>>();
    scan2_kernel<<<1, 32>>>(NCH);
    scan3_kernel<<<(N_NODES + 255) / 256, 256>>>();
    scatter_kernel<<<(ET + 255) / 256, 256>>>(ei);

    // Layer 1
    gemm1_kernel<<<dim3((N_NODES + 63) / 64, 1), 256>>>(x, W1);
    scores1_kernel<<<(N_NODES * 32 + 255) / 256, 256>>>(as1, ad1);
    agg1_kernel<<<N_NODES, 128>>>(b1);

    // Layer 2
    gemm2_kernel<<<dim3((N_NODES + 63) / 64, 1), 256>>>(W2);
    scores2_kernel<<<(N_NODES * 32 + 255) / 256, 256>>>(as2, ad2);
    agg2_kernel<<<N_NODES, 64>>>(b2, out);
}

// round 4
// speedup vs baseline: 1.3053x; 1.3053x over previous
#include <cuda_runtime.h>
#include <math.h>

#define N_NODES 50000
#define N_EDGES 800000
#define ET (N_EDGES + N_NODES)

// ---------------- scratch (static device globals; no allocation) ----------------
__device__ float g_h1[(size_t)N_NODES * 128];    // x @ W1
__device__ float g_out1[(size_t)N_NODES * 128];  // layer1 output (post bias+relu)
__device__ float g_h2[(size_t)N_NODES * 64];     // out1 @ W2
__device__ float g_ss1[N_NODES * 4];
__device__ float g_sd1[N_NODES * 4];
__device__ float g_ss2[N_NODES];
__device__ float g_sd2[N_NODES];
__device__ int   g_deg[N_NODES];
__device__ int   g_off[N_NODES + 1];
__device__ int   g_pos[N_NODES];
__device__ int   g_esrc[ET];
__device__ int   g_chunk[64];

__device__ __forceinline__ float lrelu(float x) {
    return x > 0.f ? x : 0.2f * x;
}

// edge_index arrives as int32 on device (int64 -> int32 by harness contract).
__device__ __forceinline__ void get_edge(const int* __restrict__ ei, int i,
                                         int& s, int& d) {
    if (i < N_EDGES) {
        s = ei[i];
        d = ei[N_EDGES + i];
        s = min(max(s, 0), N_NODES - 1);
        d = min(max(d, 0), N_NODES - 1);
    } else {
        s = d = i - N_EDGES;
    }
}

// ---------------- CSR build ----------------
__global__ void zero_deg_kernel() {
    int i = blockIdx.x * blockDim.x + threadIdx.x;
    if (i < N_NODES) g_deg[i] = 0;
}

__global__ void hist_kernel(const int* __restrict__ ei) {
    int i = blockIdx.x * blockDim.x + threadIdx.x;
    if (i < ET) {
        int s, d;
        get_edge(ei, i, s, d);
        atomicAdd(&g_deg[d], 1);
    }
}

__global__ void scan1_kernel() {
    __shared__ int sm[1024];
    int i = blockIdx.x * 1024 + threadIdx.x;
    int v = (i < N_NODES) ? g_deg[i] : 0;
    sm[threadIdx.x] = v;
    __syncthreads();
#pragma unroll
    for (int o = 1; o < 1024; o <<= 1) {
        int t = (threadIdx.x >= o) ? sm[threadIdx.x - o] : 0;
        __syncthreads();
        sm[threadIdx.x] += t;
        __syncthreads();
    }
    if (i < N_NODES) g_off[i] = sm[threadIdx.x] - v;  // exclusive within chunk
    if (threadIdx.x == 1023) g_chunk[blockIdx.x] = sm[1023];
}

__global__ void scan2_kernel(int nch) {
    __shared__ int sm[64];
    int t = threadIdx.x;
    int v = (t < nch) ? g_chunk[t] : 0;
    sm[t] = v;
    __syncthreads();
#pragma unroll
    for (int o = 1; o < 64; o <<= 1) {
        int u = (t >= o) ? sm[t - o] : 0;
        __syncthreads();
        sm[t] += u;
        __syncthreads();
    }
    if (t < nch) g_chunk[t] = sm[t] - v;  // exclusive
}

__global__ void scan3_kernel() {
    int i = blockIdx.x * blockDim.x + threadIdx.x;
    if (i < N_NODES) {
        g_off[i] += g_chunk[i >> 10];
        g_pos[i] = 0;
    }
    if (i == 0) g_off[N_NODES] = ET;
}

__global__ void scatter_kernel(const int* __restrict__ ei) {
    int i = blockIdx.x * blockDim.x + threadIdx.x;
    if (i < ET) {
        int s, d;
        get_edge(ei, i, s, d);
        int p = atomicAdd(&g_pos[d], 1);
        g_esrc[g_off[d] + p] = s;
    }
}

// ---------------- GEMM1 fused with scores1 ----------------
// C[M,128] = A[M,128] @ W1[128,128]; then ss1/sd1 dot products from the tile.
// BM=128, BN=128, BK=16, TM=8, TN=8, 256 threads.
__global__ void __launch_bounds__(256)
gemm1_kernel(const float* __restrict__ A, const float* __restrict__ B,
             const float* __restrict__ a_src, const float* __restrict__ a_dst) {
    constexpr int BM = 128, BN = 128, BK = 16, TM = 8, TN = 8;
    const int M = N_NODES, N = 128, K = 128;
    __shared__ float As[BK][BM];
    __shared__ float Bs[BK][BN];
    const int tid = threadIdx.x;
    const int row0 = blockIdx.x * BM;
    const int tr = tid / 16;  // 0..15
    const int tc = tid % 16;  // 0..15

    float acc[TM][TN] = {};

    for (int kt = 0; kt < K; kt += BK) {
#pragma unroll
        for (int i = 0; i < 2; i++) {
            int idx = (tid + i * 256) * 4;
            int am = idx / BK, ak = idx % BK;
            float4 v = make_float4(0.f, 0.f, 0.f, 0.f);
            if (row0 + am < M)
                v = *(const float4*)(A + (size_t)(row0 + am) * K + kt + ak);
            As[ak + 0][am] = v.x;
            As[ak + 1][am] = v.y;
            As[ak + 2][am] = v.z;
            As[ak + 3][am] = v.w;
        }
#pragma unroll
        for (int i = 0; i < 2; i++) {
            int idx = (tid + i * 256) * 4;
            int bk = idx / BN, bn = idx % BN;
            *(float4*)&Bs[bk][bn] = *(const float4*)(B + (size_t)(kt + bk) * N + bn);
        }
        __syncthreads();
#pragma unroll
        for (int k = 0; k < BK; k++) {
            float ra[TM], rb[TN];
#pragma unroll
            for (int i = 0; i < TM; i++) ra[i] = As[k][tr * TM + i];
#pragma unroll
            for (int j = 0; j < TN; j++) rb[j] = Bs[k][tc * TN + j];
#pragma unroll
            for (int i = 0; i < TM; i++)
#pragma unroll
                for (int j = 0; j < TN; j++) acc[i][j] = fmaf(ra[i], rb[j], acc[i][j]);
        }
        __syncthreads();
    }

    // attention vectors for this thread's 8 columns (flat col = head*32 + ch)
    const int head = tc >> 2;  // cols tc*8..tc*8+7 lie in head tc/4
    float av[TN], dv[TN];
#pragma unroll
    for (int j = 0; j < TN; j++) {
        av[j] = a_src[tc * TN + j];
        dv[j] = a_dst[tc * TN + j];
    }

#pragma unroll
    for (int i = 0; i < TM; i++) {
        int row = row0 + tr * TM + i;
        float ps = 0.f, pd = 0.f;
#pragma unroll
        for (int j = 0; j < TN; j++) {
            ps = fmaf(acc[i][j], av[j], ps);
            pd = fmaf(acc[i][j], dv[j], pd);
        }
        // reduce over the 4 tc's sharing this head (consecutive lanes)
        ps += __shfl_xor_sync(0xffffffffu, ps, 1);
        ps += __shfl_xor_sync(0xffffffffu, ps, 2);
        pd += __shfl_xor_sync(0xffffffffu, pd, 1);
        pd += __shfl_xor_sync(0xffffffffu, pd, 2);
        if (row < M) {
            if ((tc & 3) == 0) {
                g_ss1[row * 4 + head] = ps;
                g_sd1[row * 4 + head] = pd;
            }
#pragma unroll
            for (int j = 0; j < TN; j += 4) {
                float4 v = make_float4(acc[i][j], acc[i][j + 1], acc[i][j + 2],
                                       acc[i][j + 3]);
                *(float4*)(g_h1 + (size_t)row * N + tc * TN + j) = v;
            }
        }
    }
}

// ---------------- GEMM2 fused with scores2 ----------------
// C[M,64] = out1[M,128] @ W2[128,64]; 1 head over all 64 cols.
// BM=128, BN=64, BK=16, TM=8, TN=4, 256 threads.
__global__ void __launch_bounds__(256)
gemm2_kernel(const float* __restrict__ B, const float* __restrict__ a_src,
             const float* __restrict__ a_dst) {
    constexpr int BM = 128, BN = 64, BK = 16, TM = 8, TN = 4;
    const int M = N_NODES, N = 64, K = 128;
    const float* A = g_out1;
    __shared__ float As[BK][BM];
    __shared__ float Bs[BK][BN];
    const int tid = threadIdx.x;
    const int row0 = blockIdx.x * BM;
    const int tr = tid / 16;
    const int tc = tid % 16;

    float acc[TM][TN] = {};

    for (int kt = 0; kt < K; kt += BK) {
#pragma unroll
        for (int i = 0; i < 2; i++) {
            int idx = (tid + i * 256) * 4;
            int am = idx / BK, ak = idx % BK;
            float4 v = make_float4(0.f, 0.f, 0.f, 0.f);
            if (row0 + am < M)
                v = *(const float4*)(A + (size_t)(row0 + am) * K + kt + ak);
            As[ak + 0][am] = v.x;
            As[ak + 1][am] = v.y;
            As[ak + 2][am] = v.z;
            As[ak + 3][am] = v.w;
        }
        {
            int idx = tid * 4;
            int bk = idx / BN, bn = idx % BN;
            *(float4*)&Bs[bk][bn] = *(const float4*)(B + (size_t)(kt + bk) * N + bn);
        }
        __syncthreads();
#pragma unroll
        for (int k = 0; k < BK; k++) {
            float ra[TM], rb[TN];
#pragma unroll
            for (int i = 0; i < TM; i++) ra[i] = As[k][tr * TM + i];
#pragma unroll
            for (int j = 0; j < TN; j++) rb[j] = Bs[k][tc * TN + j];
#pragma unroll
            for (int i = 0; i < TM; i++)
#pragma unroll
                for (int j = 0; j < TN; j++) acc[i][j] = fmaf(ra[i], rb[j], acc[i][j]);
        }
        __syncthreads();
    }

    float av[TN], dv[TN];
#pragma unroll
    for (int j = 0; j < TN; j++) {
        av[j] = a_src[tc * TN + j];
        dv[j] = a_dst[tc * TN + j];
    }

#pragma unroll
    for (int i = 0; i < TM; i++) {
        int row = row0 + tr * TM + i;
        float ps = 0.f, pd = 0.f;
#pragma unroll
        for (int j = 0; j < TN; j++) {
            ps = fmaf(acc[i][j], av[j], ps);
            pd = fmaf(acc[i][j], dv[j], pd);
        }
        // reduce over all 16 tc lanes (same tr within half-warp)
        ps += __shfl_xor_sync(0xffffffffu, ps, 1);
        ps += __shfl_xor_sync(0xffffffffu, ps, 2);
        ps += __shfl_xor_sync(0xffffffffu, ps, 4);
        ps += __shfl_xor_sync(0xffffffffu, ps, 8);
        pd += __shfl_xor_sync(0xffffffffu, pd, 1);
        pd += __shfl_xor_sync(0xffffffffu, pd, 2);
        pd += __shfl_xor_sync(0xffffffffu, pd, 4);
        pd += __shfl_xor_sync(0xffffffffu, pd, 8);
        if (row < M) {
            if (tc == 0) {
                g_ss2[row] = ps;
                g_sd2[row] = pd;
            }
            float4 v = make_float4(acc[i][0], acc[i][1], acc[i][2], acc[i][3]);
            *(float4*)(g_h2 + (size_t)row * N + tc * TN) = v;
        }
    }
}

// ---------------- aggregation layer 1 ----------------
// One block (128 threads) per node. Warp w owns head w for softmax stats/alpha.
// Channel tid (0..127) maps to head tid/32 == warp id.
__global__ void agg1_kernel(const float* __restrict__ bias) {
    const int n = blockIdx.x;
    const int tid = threadIdx.x;
    const int w = tid >> 5;
    const int lane = tid & 31;
    const int beg = g_off[n];
    const int deg = g_off[n + 1] - beg;

    __shared__ int   sh_src[32];
    __shared__ float sh_alpha[4][32];

    const float sd = g_sd1[n * 4 + w];
    float m = -1e30f, dsum = 0.f;
    for (int j = lane; j < deg; j += 32) {
        int s = g_esrc[beg + j];
        float e = lrelu(g_ss1[s * 4 + w] + sd);
        if (e > m) { dsum = dsum * __expf(m - e) + 1.f; m = e; }
        else       { dsum += __expf(e - m); }
    }
#pragma unroll
    for (int o = 16; o; o >>= 1) {
        float mo = __shfl_xor_sync(0xffffffffu, m, o);
        float dd = __shfl_xor_sync(0xffffffffu, dsum, o);
        float mn = fmaxf(m, mo);
        dsum = dsum * __expf(m - mn) + dd * __expf(mo - mn);
        m = mn;
    }
    const float inv = 1.f / dsum;

    float acc = 0.f;
    for (int j0 = 0; j0 < deg; j0 += 32) {
        int cnt = min(32, deg - j0);
        __syncthreads();
        if (lane < cnt) {
            int s = g_esrc[beg + j0 + lane];
            if (w == 0) sh_src[lane] = s;
            sh_alpha[w][lane] = __expf(lrelu(g_ss1[s * 4 + w] + sd) - m) * inv;
        }
        __syncthreads();
#pragma unroll 4
        for (int j = 0; j < cnt; j++) {
            acc = fmaf(sh_alpha[w][j], g_h1[(size_t)sh_src[j] * 128 + tid], acc);
        }
    }
    g_out1[(size_t)n * 128 + tid] = fmaxf(acc + bias[tid], 0.f);
}

// ---------------- aggregation layer 2 (warp-per-node, no barriers) ----------------
__global__ void agg2_kernel(const float* __restrict__ bias, float* __restrict__ out) {
    const int gid = blockIdx.x * blockDim.x + threadIdx.x;
    const int n = gid >> 5;
    const int lane = threadIdx.x & 31;
    if (n >= N_NODES) return;
    const int beg = g_off[n];
    const int deg = g_off[n + 1] - beg;

    const float sd = g_sd2[n];
    float m = -1e30f, dsum = 0.f;
    for (int j = lane; j < deg; j += 32) {
        int s = g_esrc[beg + j];
        float e = lrelu(g_ss2[s] + sd);
        if (e > m) { dsum = dsum * __expf(m - e) + 1.f; m = e; }
        else       { dsum += __expf(e - m); }
    }
#pragma unroll
    for (int o = 16; o; o >>= 1) {
        float mo = __shfl_xor_sync(0xffffffffu, m, o);
        float dd = __shfl_xor_sync(0xffffffffu, dsum, o);
        float mn = fmaxf(m, mo);
        dsum = dsum * __expf(m - mn) + dd * __expf(mo - mn);
        m = mn;
    }
    const float inv = 1.f / dsum;

    float ax = 0.f, ay = 0.f;
    for (int j0 = 0; j0 < deg; j0 += 32) {
        int cnt = min(32, deg - j0);
        int s = 0;
        float a = 0.f;
        if (lane < cnt) {
            s = g_esrc[beg + j0 + lane];
            a = __expf(lrelu(g_ss2[s] + sd) - m) * inv;
        }
        for (int j = 0; j < cnt; j++) {
            int sj  = __shfl_sync(0xffffffffu, s, j);
            float aj = __shfl_sync(0xffffffffu, a, j);
            float2 v = *(const float2*)&g_h2[(size_t)sj * 64 + lane * 2];
            ax = fmaf(aj, v.x, ax);
            ay = fmaf(aj, v.y, ay);
        }
    }
    float2 b = *(const float2*)&bias[lane * 2];
    float2 r = make_float2(ax + b.x, ay + b.y);
    *(float2*)&out[(size_t)n * 64 + lane * 2] = r;
}

// ---------------- launch ----------------
extern "C" void kernel_launch(void* const* d_in, const int* in_sizes, int n_in,
                              void* d_out, int out_size) {
    const float* x   = (const float*)d_in[0];
    const int*   ei  = (const int*)d_in[1];   // int64 in reference -> int32 on device
    const float* W1  = (const float*)d_in[2];
    const float* as1 = (const float*)d_in[3];
    const float* ad1 = (const float*)d_in[4];
    const float* b1  = (const float*)d_in[5];
    const float* W2  = (const float*)d_in[6];
    const float* as2 = (const float*)d_in[7];
    const float* ad2 = (const float*)d_in[8];
    const float* b2  = (const float*)d_in[9];
    float* out = (float*)d_out;

    const int NCH = (N_NODES + 1023) / 1024;  // 49

    // CSR build
    zero_deg_kernel<<<(N_NODES + 255) / 256, 256>>>();
    hist_kernel<<<(ET + 255) / 256, 256>>>(ei);
    scan1_kernel<<<NCH, 1024>>>();
    scan2_kernel<<<1, 64>>>(NCH);
    scan3_kernel<<<(N_NODES + 255) / 256, 256>>>();
    scatter_kernel<<<(ET + 255) / 256, 256>>>(ei);

    // Layer 1: GEMM + fused scores, then aggregate (+bias+relu)
    gemm1_kernel<<<(N_NODES + 127) / 128, 256>>>(x, W1, as1, ad1);
    agg1_kernel<<<N_NODES, 128>>>(b1);

    // Layer 2: GEMM + fused scores, then aggregate (+bias) -> out
    gemm2_kernel<<<(N_NODES + 127) / 128, 256>>>(W2, as2, ad2);
    agg2_kernel<<<(N_NODES * 32 + 255) / 256, 256>>>(b2, out);
}